// round 2
// baseline (speedup 1.0000x reference)
#include <cuda_runtime.h>
#include <math.h>

#define NB      1805      // 5*19*19 boxes per batch
#define SORT_N  2048
#define NT      1024
#define NBP     1808      // padded

__device__ int g_acc[3];  // [0]=total_gt, [1]=proposals, [2]=correct

__constant__ float ANCW[5] = {1.3221f, 3.19275f, 5.05587f, 9.47112f, 11.2364f};
__constant__ float ANCH[5] = {1.73145f, 4.00944f, 8.09892f, 4.84053f, 10.0071f};

__device__ __forceinline__ float sigm(float x) { return 1.0f / (1.0f + expf(-x)); }

// cxcywh IoU, exact port of reference pairwise_iou
__device__ __forceinline__ float iou_cc(float ax, float ay, float aw, float ah,
                                        float bx, float by, float bw, float bh) {
    float ax1 = ax - aw * 0.5f, ax2 = ax + aw * 0.5f;
    float ay1 = ay - ah * 0.5f, ay2 = ay + ah * 0.5f;
    float bx1 = bx - bw * 0.5f, bx2 = bx + bw * 0.5f;
    float by1 = by - bh * 0.5f, by2 = by + bh * 0.5f;
    float uw = fmaxf(ax2, bx2) - fminf(ax1, bx1);
    float uh = fmaxf(ay2, by2) - fminf(ay1, by1);
    float cw = aw + bw - uw;
    float ch = ah + bh - uh;
    float carea = (cw > 0.0f && ch > 0.0f) ? cw * ch : 0.0f;
    float uarea = aw * ah + bw * bh - carea;
    return carea / uarea;
}

__global__ void zero_acc_kernel() {
    if (threadIdx.x < 3) g_acc[threadIdx.x] = 0;
}

__global__ __launch_bounds__(NT) void yolo_recall_kernel(
    const float* __restrict__ out,   // [8, 125, 19, 19]
    const float* __restrict__ tgt)   // [8, 250]
{
    __shared__ float skey[SORT_N];
    __shared__ int   sidx[SORT_N];
    __shared__ float sbx[NBP], sby[NBP], sbw[NBP], sbh[NBP];
    __shared__ unsigned char keep[NBP];
    __shared__ float sgt[250];
    __shared__ unsigned char sgv[52];
    __shared__ int sM, sI, sProp;

    const int b = blockIdx.x;
    const int tid = threadIdx.x;
    const float* ob = out + (size_t)b * 125 * 361;

    // --- 1. conf (sigmoid of channel 4) + index; pad with -1 ---
    for (int r = tid; r < SORT_N; r += NT) {
        if (r < NB) {
            int a = r / 361, rem = r - a * 361;
            skey[r] = sigm(ob[(a * 25 + 4) * 361 + rem]);
            sidx[r] = r;
        } else {
            skey[r] = -1.0f;
            sidx[r] = -1;
        }
    }
    if (tid == 0) { sM = 0; sProp = 0; }
    __syncthreads();

    // --- 2. bitonic sort (descending by key), 2048 elems, 1024 threads ---
    for (int k = 2; k <= SORT_N; k <<= 1) {
        for (int j = k >> 1; j > 0; j >>= 1) {
            int i = ((tid & ~(j - 1)) << 1) | (tid & (j - 1));
            int p = i | j;
            bool up = (i & k) == 0;  // descending run
            float ki = skey[i], kp = skey[p];
            if (up ? (ki < kp) : (ki > kp)) {
                skey[i] = kp; skey[p] = ki;
                int q = sidx[i]; sidx[i] = sidx[p]; sidx[p] = q;
            }
            __syncthreads();
        }
    }

    // --- 3. M = count(conf > 0.5) = boundary in sorted keys ---
    for (int r = tid; r < SORT_N; r += NT) {
        float kt = skey[r];
        float kn = (r + 1 < SORT_N) ? skey[r + 1] : -2.0f;
        if (kt > 0.5f && kn <= 0.5f) sM = r + 1;
    }
    __syncthreads();
    const int M = sM;

    // --- 4. decode boxes only for the valid prefix ---
    for (int r = tid; r < M; r += NT) {
        int n = sidx[r];
        int a = n / 361, rem = n - a * 361;
        int h = rem / 19, w = rem - h * 19;
        const float* p = ob + (a * 25) * 361 + rem;
        float o0 = p[0], o1 = p[361], o2 = p[722], o3 = p[1083];
        sbx[r] = (sigm(o0) + (float)w) / 19.0f;
        sby[r] = (sigm(o1) + (float)h) / 19.0f;
        sbw[r] = expf(o2) * (ANCW[a] / 19.0f);
        sbh[r] = expf(o3) * (ANCH[a] / 19.0f);
        keep[r] = 1;
    }
    __syncthreads();

    // --- 5. greedy NMS over sorted valid prefix ---
    int nextc = 0;  // cursor, only used by tid 0
    while (true) {
        if (tid == 0) {
            int c = nextc;
            while (c < M && !keep[c]) c++;
            sI = c;
        }
        __syncthreads();
        int i = sI;
        if (i >= M) break;
        float bix = sbx[i], biy = sby[i], biw = sbw[i], bih = sbh[i];
        for (int r = i + 1 + tid; r < M; r += NT) {
            if (keep[r] &&
                iou_cc(bix, biy, biw, bih, sbx[r], sby[r], sbw[r], sbh[r]) > 0.45f)
                keep[r] = 0;
        }
        nextc = i + 1;
        __syncthreads();
    }

    // --- 6. proposals count ---
    int cnt = 0;
    for (int r = tid; r < M; r += NT) cnt += keep[r];
    #pragma unroll
    for (int o = 16; o; o >>= 1) cnt += __shfl_xor_sync(0xFFFFFFFFu, cnt, o);
    if ((tid & 31) == 0 && cnt) atomicAdd(&sProp, cnt);
    __syncthreads();
    if (tid == 0 && sProp) atomicAdd(&g_acc[1], sProp);

    // --- 7. ground truth: validity prefix + total ---
    for (int t = tid; t < 250; t += NT) sgt[t] = tgt[b * 250 + t];
    __syncthreads();
    if (tid == 0) {
        int v = 1, totb = 0;
        for (int t = 0; t < 50; t++) {
            if (sgt[t * 5 + 1] == 0.0f) v = 0;
            sgv[t] = (unsigned char)v;
            totb += v;
        }
        if (totb) atomicAdd(&g_acc[0], totb);
    }
    __syncthreads();

    // --- 8. per-GT max IoU over kept boxes: one warp per GT row ---
    int warp = tid >> 5, lane = tid & 31;
    for (int t = warp; t < 50; t += 32) {
        float gx = sgt[t * 5 + 1], gy = sgt[t * 5 + 2];
        float gw = sgt[t * 5 + 3], gh = sgt[t * 5 + 4];
        float m = 0.0f;
        for (int r = lane; r < M; r += 32) {
            if (keep[r])
                m = fmaxf(m, iou_cc(gx, gy, gw, gh, sbx[r], sby[r], sbw[r], sbh[r]));
        }
        #pragma unroll
        for (int o = 16; o; o >>= 1)
            m = fmaxf(m, __shfl_xor_sync(0xFFFFFFFFu, m, o));
        if (lane == 0 && sgv[t] && m > 0.5f) atomicAdd(&g_acc[2], 1);
    }
}

__global__ void finalize_kernel(float* __restrict__ out) {
    float t = (float)g_acc[0];
    float p = (float)g_acc[1];
    float c = (float)g_acc[2];
    float prec = c / (p + 1e-6f);
    float rec  = c / (t + 1e-6f);
    float f    = 2.0f * prec * rec / (prec + rec + 1e-6f);
    out[0] = t; out[1] = p; out[2] = c;
    out[3] = prec; out[4] = rec; out[5] = f;
}

extern "C" void kernel_launch(void* const* d_in, const int* in_sizes, int n_in,
                              void* d_out, int out_size) {
    const float* output = (const float*)d_in[0];  // [8,125,19,19]
    const float* target = (const float*)d_in[1];  // [8,250]
    zero_acc_kernel<<<1, 32>>>();
    yolo_recall_kernel<<<8, NT>>>(output, target);
    finalize_kernel<<<1, 1>>>((float*)d_out);
}

// round 4
// speedup vs baseline: 3.0186x; 3.0186x over previous
#include <cuda_runtime.h>
#include <math.h>

#define NB     1805          // 5*19*19 boxes per batch
#define SORT_N 2048
#define NW64   29            // ceil(1805/64) uint64 words per mask row
#define NW32   58            // = 2*NW64 (uint32 view, even for alignment)

__device__ float g_boxes[8][NB][8];                    // x1,x2,y1,y2,w,h,0,0
__device__ int   g_M[8];
__device__ unsigned long long g_mask[8ULL * NB * NW64]; // ~3.35MB, zero-init
__device__ int   g_part[8][3];
__device__ int   g_ticket = 0;

__constant__ float ANCW[5] = {1.3221f, 3.19275f, 5.05587f, 9.47112f, 11.2364f};
__constant__ float ANCH[5] = {1.73145f, 4.00944f, 8.09892f, 4.84053f, 10.0071f};

// division-free IoU>thr test; A0/B0 = {x1,x2,y1,y2}, A1/B1 = {w,h,-,-}
__device__ __forceinline__ bool sup_pair(float4 A0, float4 A1,
                                         float4 B0, float4 B1, float thr) {
    float uw = fmaxf(A0.y, B0.y) - fminf(A0.x, B0.x);
    float uh = fmaxf(A0.w, B0.w) - fminf(A0.z, B0.z);
    float cw = A1.x + B1.x - uw;
    float ch = A1.y + B1.y - uh;
    float carea = (cw > 0.0f && ch > 0.0f) ? cw * ch : 0.0f;
    float uarea = A1.x * A1.y + B1.x * B1.y - carea;
    return carea > thr * uarea;        // uarea > 0 always (w,h > 0)
}

// ---------------- Kernel A: conf sort + decode --------------------------
__global__ __launch_bounds__(1024) void decode_sort_kernel(
    const float* __restrict__ out)     // [8,125,19,19]
{
    __shared__ float skey[SORT_N];
    __shared__ int   sidx[SORT_N];
    __shared__ int   sCnt;

    const int b = blockIdx.x, tid = threadIdx.x;
    const float* ob = out + (size_t)b * 125 * 361;

    if (tid == 0) sCnt = 0;
    __syncthreads();

    int cnt = 0;
    for (int r = tid; r < SORT_N; r += 1024) {
        if (r < NB) {
            int a = r / 361, rem = r - a * 361;
            float lg = ob[(a * 25 + 4) * 361 + rem];   // raw logit; sigmoid monotone
            skey[r] = lg; sidx[r] = r;
            if (lg > 0.0f) cnt++;                      // sigmoid(lg) > 0.5
        } else { skey[r] = -1e30f; sidx[r] = -1; }
    }
    #pragma unroll
    for (int o = 16; o; o >>= 1) cnt += __shfl_xor_sync(0xffffffffu, cnt, o);
    if ((tid & 31) == 0 && cnt) atomicAdd(&sCnt, cnt);
    __syncthreads();
    if (tid == 0) g_M[b] = sCnt;
    const int M = sCnt;

    // bitonic sort descending (2048 elems, 1024 threads)
    for (int k = 2; k <= SORT_N; k <<= 1) {
        for (int j = k >> 1; j > 0; j >>= 1) {
            int i = ((tid & ~(j - 1)) << 1) | (tid & (j - 1));
            int p = i | j;
            bool up = (i & k) == 0;
            float ki = skey[i], kp = skey[p];
            if (up ? (ki < kp) : (ki > kp)) {
                skey[i] = kp; skey[p] = ki;
                int q = sidx[i]; sidx[i] = sidx[p]; sidx[p] = q;
            }
            __syncthreads();
        }
    }

    // decode the valid prefix only
    for (int r = tid; r < M; r += 1024) {
        int n = sidx[r];
        int a = n / 361, rem = n - a * 361;
        int hh = rem / 19, ww = rem - hh * 19;
        const float* p = ob + (a * 25) * 361 + rem;
        float cx = (1.0f / (1.0f + expf(-p[0]))   + (float)ww) / 19.0f;
        float cy = (1.0f / (1.0f + expf(-p[361])) + (float)hh) / 19.0f;
        float bw = expf(p[722])  * (ANCW[a] / 19.0f);
        float bh = expf(p[1083]) * (ANCH[a] / 19.0f);
        float4 v0 = make_float4(cx - bw * 0.5f, cx + bw * 0.5f,
                                cy - bh * 0.5f, cy + bh * 0.5f);
        float4 v1 = make_float4(bw, bh, 0.0f, 0.0f);
        *(float4*)&g_boxes[b][r][0] = v0;
        *(float4*)&g_boxes[b][r][4] = v1;
    }
}

// ---------------- Kernel B: suppression bitmask build -------------------
__global__ __launch_bounds__(256) void mask_kernel() {
    const int b = blockIdx.y;
    const int M = g_M[b];
    const int tile0 = blockIdx.x * 128;
    if (tile0 >= M) return;

    const int warp = threadIdx.x >> 5, lane = threadIdx.x & 31;
    const int tend = min(tile0 + 128, M);
    unsigned* mask32 = (unsigned*)g_mask;

    for (int r0 = tile0 + warp * 4; r0 < tend; r0 += 32) {
        float4 R0[4], R1[4];
        #pragma unroll
        for (int d = 0; d < 4; d++) {
            int i = min(r0 + d, M - 1);
            R0[d] = *(const float4*)&g_boxes[b][i][0];
            R1[d] = *(const float4*)&g_boxes[b][i][4];
        }
        const int whi = (M + 31) >> 5;
        for (int w = r0 >> 5; w < whi; w++) {
            int j  = (w << 5) + lane;
            int jc = min(j, M - 1);
            float4 C0 = *(const float4*)&g_boxes[b][jc][0];
            float4 C1 = *(const float4*)&g_boxes[b][jc][4];
            #pragma unroll
            for (int d = 0; d < 4; d++) {
                int i = r0 + d;
                bool s = (j > i) && (j < M) && (i < M) &&
                         sup_pair(R0[d], R1[d], C0, C1, 0.45f);
                unsigned bal = __ballot_sync(0xffffffffu, s);
                if (lane == d && i < M)
                    mask32[((size_t)(b * NB + i)) * NW32 + w] = bal;
            }
        }
    }
}

// ---------------- Kernel C: warp-serial scan + stats + finalize ---------
__global__ __launch_bounds__(256) void scan_stats_kernel(
    const float* __restrict__ tgt, float* __restrict__ outp)
{
    __shared__ unsigned long long skeep[32];
    __shared__ float sgt[250];
    __shared__ unsigned char sgv[52];
    __shared__ int sTot, sProp, sCorr;

    const int b = blockIdx.x, tid = threadIdx.x;
    const int lane = tid & 31, warp = tid >> 5;
    const int M = g_M[b];

    if (tid == 0) sCorr = 0;
    for (int t = tid; t < 250; t += 256) sgt[t] = tgt[b * 250 + t];
    __syncthreads();

    if (tid == 32) {   // warp 1: GT validity (concurrent with warp-0 scan)
        int v = 1, tb = 0;
        for (int t = 0; t < 50; t++) {
            if (sgt[t * 5 + 1] == 0.0f) v = 0;
            sgv[t] = (unsigned char)v; tb += v;
        }
        sTot = tb;
    }

    if (warp == 0) {   // greedy NMS: SHFL-chained bitmask scan, 8-deep pipeline
        const unsigned long long* mb = g_mask + (size_t)b * NB * NW64;
        unsigned long long removed = 0ULL, cur[8], nxt[8];
        #pragma unroll
        for (int d = 0; d < 8; d++)
            cur[d] = (d < M && lane < NW64) ? mb[(size_t)d * NW64 + lane] : 0ULL;
        for (int base = 0; base < M; base += 8) {
            #pragma unroll
            for (int d = 0; d < 8; d++) {
                int i = base + 8 + d;
                nxt[d] = (i < M && lane < NW64) ? mb[(size_t)i * NW64 + lane] : 0ULL;
            }
            #pragma unroll
            for (int d = 0; d < 8; d++) {
                int i = base + d;
                if (i < M) {
                    unsigned long long wv = __shfl_sync(0xffffffffu, removed, i >> 6);
                    if (!((wv >> (i & 63)) & 1ULL)) removed |= cur[d];
                }
            }
            #pragma unroll
            for (int d = 0; d < 8; d++) cur[d] = nxt[d];
        }
        skeep[lane] = (lane < NW64) ? removed : 0ULL;
        int pc = (lane < NW64) ? __popcll(removed) : 0;
        #pragma unroll
        for (int o = 16; o; o >>= 1) pc += __shfl_xor_sync(0xffffffffu, pc, o);
        if (lane == 0) sProp = M - pc;
    }
    __syncthreads();

    // GT matching: warp per GT row, division-free any(IoU>0.5)
    for (int t = warp; t < 50; t += 8) {
        float gx = sgt[t * 5 + 1], gy = sgt[t * 5 + 2];
        float gw = sgt[t * 5 + 3], gh = sgt[t * 5 + 4];
        float4 G0 = make_float4(gx - gw * 0.5f, gx + gw * 0.5f,
                                gy - gh * 0.5f, gy + gh * 0.5f);
        float4 G1 = make_float4(gw, gh, 0.0f, 0.0f);
        bool any = false;
        for (int j = lane; j < M; j += 32) {
            if (!((skeep[j >> 6] >> (j & 63)) & 1ULL)) {
                float4 C0 = *(const float4*)&g_boxes[b][j][0];
                float4 C1 = *(const float4*)&g_boxes[b][j][4];
                any |= sup_pair(G0, G1, C0, C1, 0.5f);
            }
        }
        unsigned bal = __ballot_sync(0xffffffffu, any);
        if (lane == 0 && sgv[t] && bal) atomicAdd(&sCorr, 1);
    }
    __syncthreads();

    if (tid == 0) {
        g_part[b][0] = sTot; g_part[b][1] = sProp; g_part[b][2] = sCorr;
        __threadfence();
        int tk = atomicAdd(&g_ticket, 1);
        if (tk == 7) {                 // last block finalizes
            __threadfence();
            int T = 0, P = 0, C = 0;
            for (int i = 0; i < 8; i++) {
                T += g_part[i][0]; P += g_part[i][1]; C += g_part[i][2];
            }
            float tf = (float)T, pf = (float)P, cf = (float)C;
            float prec = cf / (pf + 1e-6f);
            float rec  = cf / (tf + 1e-6f);
            float f    = 2.0f * prec * rec / (prec + rec + 1e-6f);
            outp[0] = tf; outp[1] = pf; outp[2] = cf;
            outp[3] = prec; outp[4] = rec; outp[5] = f;
            atomicExch(&g_ticket, 0);  // reset for next replay
        }
    }
}

extern "C" void kernel_launch(void* const* d_in, const int* in_sizes, int n_in,
                              void* d_out, int out_size) {
    const float* output = (const float*)d_in[0];  // [8,125,19,19]
    const float* target = (const float*)d_in[1];  // [8,250]
    decode_sort_kernel<<<8, 1024>>>(output);
    mask_kernel<<<dim3(15, 8), 256>>>();
    scan_stats_kernel<<<8, 256>>>(target, (float*)d_out);
}

// round 5
// speedup vs baseline: 3.0885x; 1.0231x over previous
#include <cuda_runtime.h>
#include <math.h>

#define NB     1805          // 5*19*19 boxes per batch
#define NKPAD  1824          // keys padded to multiple of 4
#define NW64   29            // ceil(1805/64) u64 words per mask row
#define NW32   58            // u32 view

__device__ float g_boxes[8][NB][8];                      // x1,x2,y1,y2,w,h,0,0
__device__ int   g_M[8];
__device__ unsigned long long g_mask[8ULL * NB * NW64];  // ~3.35MB, zero-init
__device__ unsigned long long g_gtm[8][50][NW64];        // GT IoU>0.5 bitmasks
__device__ int   g_part[8][3];
__device__ int   g_ticket = 0;

__constant__ float ANCW[5] = {1.3221f, 3.19275f, 5.05587f, 9.47112f, 11.2364f};
__constant__ float ANCH[5] = {1.73145f, 4.00944f, 8.09892f, 4.84053f, 10.0071f};

// division-free IoU>thr test; A0/B0 = {x1,x2,y1,y2}, A1/B1 = {w,h,-,-}
__device__ __forceinline__ bool sup_pair(float4 A0, float4 A1,
                                         float4 B0, float4 B1, float thr) {
    float uw = fmaxf(A0.y, B0.y) - fminf(A0.x, B0.x);
    float uh = fmaxf(A0.w, B0.w) - fminf(A0.z, B0.z);
    float cw = A1.x + B1.x - uw;
    float ch = A1.y + B1.y - uh;
    float carea = (cw > 0.0f && ch > 0.0f) ? cw * ch : 0.0f;
    float uarea = A1.x * A1.y + B1.x * B1.y - carea;
    return carea > thr * uarea;      // uarea > 0 (w,h > 0)
}

// ---------------- Kernel A: rank-based sort + decode (no barriers/bitonic) ---
__global__ __launch_bounds__(256) void rank_decode_kernel(
    const float* __restrict__ out)   // [8,125,19,19]
{
    __shared__ float skey[NKPAD];
    __shared__ int sCnt;

    const int b = blockIdx.y, s = blockIdx.x, tid = threadIdx.x;
    const float* ob = out + (size_t)b * 125 * 361;

    if (tid == 0) sCnt = 0;
    for (int r = tid; r < NKPAD; r += 256) {
        if (r < NB) {
            int a = r / 361, rem = r - a * 361;
            skey[r] = ob[(a * 25 + 4) * 361 + rem];   // raw conf logit
        } else skey[r] = -1e30f;
    }
    __syncthreads();

    // count M = #(logit > 0)  (sigmoid > 0.5)
    int c = 0;
    for (int r = tid; r < NB; r += 256) if (skey[r] > 0.0f) c++;
    #pragma unroll
    for (int o = 16; o; o >>= 1) c += __shfl_xor_sync(0xffffffffu, c, o);
    if ((tid & 31) == 0 && c) atomicAdd(&sCnt, c);
    __syncthreads();
    if (s == 0 && tid == 0) g_M[b] = sCnt;

    // rank + decode one box per thread (slice of 226)
    int i = s * 226 + tid;
    if (tid < 226 && i < NB) {
        float ki = skey[i];
        if (ki > 0.0f) {
            const float4* k4 = (const float4*)skey;
            int rank = 0;
            #pragma unroll 4
            for (int w = 0; w < NKPAD / 4; w++) {
                float4 v = k4[w];
                rank += (v.x > ki) + (v.y > ki) + (v.z > ki) + (v.w > ki);
            }
            int a = i / 361, rem = i - a * 361;
            int hh = rem / 19, ww = rem - hh * 19;
            const float* p = ob + (a * 25) * 361 + rem;
            float cx = (1.0f / (1.0f + expf(-p[0]))   + (float)ww) / 19.0f;
            float cy = (1.0f / (1.0f + expf(-p[361])) + (float)hh) / 19.0f;
            float bw = expf(p[722])  * (ANCW[a] / 19.0f);
            float bh = expf(p[1083]) * (ANCH[a] / 19.0f);
            float4 v0 = make_float4(cx - bw * 0.5f, cx + bw * 0.5f,
                                    cy - bh * 0.5f, cy + bh * 0.5f);
            float4 v1 = make_float4(bw, bh, 0.0f, 0.0f);
            *(float4*)&g_boxes[b][rank][0] = v0;
            *(float4*)&g_boxes[b][rank][4] = v1;
        }
    }
}

// ---------------- Kernel B: suppression bitmask + GT bitmasks -------------
__global__ __launch_bounds__(256) void mask_kernel(const float* __restrict__ tgt)
{
    const int b = blockIdx.y;
    const int M = g_M[b];
    const int warp = threadIdx.x >> 5, lane = threadIdx.x & 31;

    if (blockIdx.x == 15) {
        // ---- GT bitmask path: task = (gt, word32), independent iterations ----
        __shared__ float sg[256];
        for (int t = threadIdx.x; t < 250; t += 256) sg[t] = tgt[b * 250 + t];
        __syncthreads();
        const int nw32 = (M + 31) >> 5;
        const int ntasks = 50 * nw32;
        unsigned* gtm32 = (unsigned*)g_gtm;
        #pragma unroll 2
        for (int task = warp; task < ntasks; task += 8) {
            int t = task / nw32, w = task - t * nw32;
            float gx = sg[t * 5 + 1], gy = sg[t * 5 + 2];
            float gw = sg[t * 5 + 3], gh = sg[t * 5 + 4];
            float4 G0 = make_float4(gx - gw * 0.5f, gx + gw * 0.5f,
                                    gy - gh * 0.5f, gy + gh * 0.5f);
            float4 G1 = make_float4(gw, gh, 0.0f, 0.0f);
            int j = (w << 5) + lane, jc = min(j, M - 1);
            float4 C0 = *(const float4*)&g_boxes[b][jc][0];
            float4 C1 = *(const float4*)&g_boxes[b][jc][4];
            bool s = (j < M) && sup_pair(G0, G1, C0, C1, 0.5f);
            unsigned bal = __ballot_sync(0xffffffffu, s);
            if (lane == 0)
                gtm32[((size_t)(b * 50 + t)) * NW32 + w] = bal;
        }
        return;
    }

    // ---- box-vs-box suppression mask path ----
    const int tile0 = blockIdx.x * 128;
    if (tile0 >= M) return;
    const int tend = min(tile0 + 128, M);
    unsigned* mask32 = (unsigned*)g_mask;

    for (int r0 = tile0 + warp * 4; r0 < tend; r0 += 32) {
        float4 R0[4], R1[4];
        #pragma unroll
        for (int d = 0; d < 4; d++) {
            int i = min(r0 + d, M - 1);
            R0[d] = *(const float4*)&g_boxes[b][i][0];
            R1[d] = *(const float4*)&g_boxes[b][i][4];
        }
        const int whi = (M + 31) >> 5;
        for (int w = r0 >> 5; w < whi; w++) {
            int j  = (w << 5) + lane;
            int jc = min(j, M - 1);
            float4 C0 = *(const float4*)&g_boxes[b][jc][0];
            float4 C1 = *(const float4*)&g_boxes[b][jc][4];
            #pragma unroll
            for (int d = 0; d < 4; d++) {
                int i = r0 + d;
                bool s = (j > i) && (j < M) && (i < M) &&
                         sup_pair(R0[d], R1[d], C0, C1, 0.45f);
                unsigned bal = __ballot_sync(0xffffffffu, s);
                if (lane == d && i < M)
                    mask32[((size_t)(b * NB + i)) * NW32 + w] = bal;
            }
        }
    }
}

// ---------------- Kernel C: chunked chain scan + stats + finalize ---------
__global__ __launch_bounds__(64) void scan_stats_kernel(
    const float* __restrict__ tgt, float* __restrict__ outp)
{
    __shared__ unsigned long long skeep[32];
    __shared__ unsigned long long sGV;       // GT validity bitmask (50 bits)
    __shared__ float sg[256];
    __shared__ int sTot, sProp, sCorr;

    const int b = blockIdx.x, tid = threadIdx.x;
    const int lane = tid & 31, warp = tid >> 5;
    const int M = g_M[b];

    if (tid == 0) sCorr = 0;
    for (int t = tid; t < 250; t += 64) sg[t] = tgt[b * 250 + t];
    __syncthreads();

    if (tid == 32) {                 // warp 1: GT validity prefix (serial 50)
        unsigned long long gv = 0ULL;
        int v = 1, tb = 0;
        for (int t = 0; t < 50; t++) {
            if (sg[t * 5 + 1] == 0.0f) v = 0;
            gv |= (unsigned long long)v << t; tb += v;
        }
        sGV = gv; sTot = tb;
    }

    if (warp == 0) {                 // greedy NMS: 8-box chunks, local decisions
        const unsigned long long* mb = g_mask + (size_t)b * NB * NW64;
        unsigned long long removed = 0ULL;
        unsigned long long cur[8], n1[8], n2[8];
        const bool ld = (lane < NW64);
        #pragma unroll
        for (int d = 0; d < 8; d++) {
            cur[d] = (ld && d      < M) ? mb[(size_t)(d)      * NW64 + lane] : 0ULL;
            n1[d]  = (ld && d + 8  < M) ? mb[(size_t)(d + 8)  * NW64 + lane] : 0ULL;
            n2[d]  = (ld && d + 16 < M) ? mb[(size_t)(d + 16) * NW64 + lane] : 0ULL;
        }
        for (int base = 0; base < M; base += 8) {
            int w0 = base >> 6;
            unsigned dec = 0;
            if (lane == w0) {        // all 8 decision bits live in word w0
                unsigned long long lw = removed;
                #pragma unroll
                for (int d = 0; d < 8; d++) {
                    int bit = (base & 63) + d;
                    if (base + d < M && !((lw >> bit) & 1ULL)) {
                        dec |= 1u << d;
                        lw |= cur[d];
                    }
                }
            }
            dec = __shfl_sync(0xffffffffu, dec, w0);
            #pragma unroll
            for (int d = 0; d < 8; d++)
                if (dec & (1u << d)) removed |= cur[d];
            #pragma unroll
            for (int d = 0; d < 8; d++) { cur[d] = n1[d]; n1[d] = n2[d]; }
            int nb2 = base + 24;
            #pragma unroll
            for (int d = 0; d < 8; d++)
                n2[d] = (ld && nb2 + d < M) ? mb[(size_t)(nb2 + d) * NW64 + lane] : 0ULL;
        }
        skeep[lane] = ld ? removed : 0ULL;
        int pc = ld ? __popcll(removed) : 0;
        #pragma unroll
        for (int o = 16; o; o >>= 1) pc += __shfl_xor_sync(0xffffffffu, pc, o);
        if (lane == 0) sProp = M - pc;
    }
    __syncthreads();

    // correct: one lane per GT, word-AND against precomputed GT masks
    if (tid < 50 && ((sGV >> tid) & 1ULL)) {
        const unsigned long long* gm = g_gtm[b][tid];
        bool any = false;
        #pragma unroll
        for (int w = 0; w < NW64; w++)
            any |= (gm[w] & ~skeep[w]) != 0ULL;
        if (any) atomicAdd(&sCorr, 1);
    }
    __syncthreads();

    if (tid == 0) {
        g_part[b][0] = sTot; g_part[b][1] = sProp; g_part[b][2] = sCorr;
        __threadfence();
        int tk = atomicAdd(&g_ticket, 1);
        if (tk == 7) {               // last block finalizes
            __threadfence();
            int T = 0, P = 0, C = 0;
            for (int i = 0; i < 8; i++) {
                T += g_part[i][0]; P += g_part[i][1]; C += g_part[i][2];
            }
            float tf = (float)T, pf = (float)P, cf = (float)C;
            float prec = cf / (pf + 1e-6f);
            float rec  = cf / (tf + 1e-6f);
            float f    = 2.0f * prec * rec / (prec + rec + 1e-6f);
            outp[0] = tf; outp[1] = pf; outp[2] = cf;
            outp[3] = prec; outp[4] = rec; outp[5] = f;
            atomicExch(&g_ticket, 0); // reset for next replay
        }
    }
}

extern "C" void kernel_launch(void* const* d_in, const int* in_sizes, int n_in,
                              void* d_out, int out_size) {
    const float* output = (const float*)d_in[0];  // [8,125,19,19]
    const float* target = (const float*)d_in[1];  // [8,250]
    rank_decode_kernel<<<dim3(8, 8), 256>>>(output);
    mask_kernel<<<dim3(16, 8), 256>>>(target);
    scan_stats_kernel<<<8, 64>>>(target, (float*)d_out);
}

// round 6
// speedup vs baseline: 3.1967x; 1.0351x over previous
#include <cuda_runtime.h>
#include <math.h>

#define NB     1805          // 5*19*19 boxes per batch
#define NKPAD  1824          // keys padded to multiple of 4
#define NW64   29            // ceil(1805/64) u64 words per mask row
#define NW32   58            // u32 view
#define NBLK   128
#define NTHR   256

__device__ float g_boxes[8][NB][8];                      // x1,x2,y1,y2,w,h,0,0
__device__ int   g_M[8];
__device__ unsigned long long g_mask[8ULL * NB * NW64];  // ~3.35MB, zero-init
__device__ unsigned long long g_gtm[8][50][NW64];        // GT IoU>0.5 bitmasks
__device__ int   g_part[8][3];
__device__ int   g_ticket = 0;
__device__ unsigned          g_count = 0;
__device__ volatile unsigned g_gen   = 0;

__constant__ float ANCW[5] = {1.3221f, 3.19275f, 5.05587f, 9.47112f, 11.2364f};
__constant__ float ANCH[5] = {1.73145f, 4.00944f, 8.09892f, 4.84053f, 10.0071f};

// IoU > thr, explicit round-to-nearest ops (no FMA contraction) + IEEE div,
// matching numpy/jax float32 evaluation order. uarea==0 -> NaN -> false.
__device__ __forceinline__ bool iou_gt(float4 A0, float4 A1,
                                       float4 B0, float4 B1, float thr) {
    float uw = __fsub_rn(fmaxf(A0.y, B0.y), fminf(A0.x, B0.x));
    float uh = __fsub_rn(fmaxf(A0.w, B0.w), fminf(A0.z, B0.z));
    float cw = __fsub_rn(__fadd_rn(A1.x, B1.x), uw);
    float ch = __fsub_rn(__fadd_rn(A1.y, B1.y), uh);
    float carea = (cw > 0.0f && ch > 0.0f) ? __fmul_rn(cw, ch) : 0.0f;
    float uarea = __fsub_rn(__fadd_rn(__fmul_rn(A1.x, A1.y),
                                      __fmul_rn(B1.x, B1.y)), carea);
    return __fdiv_rn(carea, uarea) > thr;
}

__device__ __forceinline__ void grid_sync(unsigned target) {
    __threadfence();
    __syncthreads();
    if (threadIdx.x == 0) {
        unsigned t = atomicAdd(&g_count, 1u);
        if (t == NBLK - 1) {
            g_count = 0;
            __threadfence();
            g_gen = target;
        } else {
            while (g_gen != target) __nanosleep(32);
        }
    }
    __syncthreads();
    __threadfence();
}

extern "C" __global__ void __launch_bounds__(NTHR)
fused_kernel(const float* __restrict__ out,    // [8,125,19,19]
             const float* __restrict__ tgt,    // [8,250]
             float* __restrict__ outp)         // [6]
{
    __shared__ float skey[NKPAD];
    __shared__ float sg[252];
    __shared__ unsigned long long skeep[32];
    __shared__ unsigned long long sGV;
    __shared__ unsigned sGen;
    __shared__ int sCnt, sTot, sProp, sCorr;

    const int blk = blockIdx.x;          // 0..127
    const int tid = threadIdx.x;
    const int lane = tid & 31, warp = tid >> 5;

    // ================= Phase A: rank + decode ============================
    {
        const int b = blk >> 4, s = blk & 15;
        const float* ob = out + (size_t)b * 125 * 361;

        if (tid == 0) { sGen = g_gen; sCnt = 0; }
        for (int r = tid; r < NKPAD; r += NTHR) {
            if (r < NB) {
                int a = r / 361, rem = r - a * 361;
                skey[r] = ob[(a * 25 + 4) * 361 + rem];   // raw conf logit
            } else skey[r] = -1e30f;
        }
        // GT staging for phase-B GT warps (blocks s>=12) — batch = blk>>4
        if (s >= 12)
            for (int t = tid; t < 250; t += NTHR) sg[t] = tgt[b * 250 + t];
        __syncthreads();

        if (s == 0) {                    // M = #(logit > 0) i.e. sigmoid>0.5
            int c = 0;
            for (int r = tid; r < NB; r += NTHR) if (skey[r] > 0.0f) c++;
            #pragma unroll
            for (int o = 16; o; o >>= 1) c += __shfl_xor_sync(0xffffffffu, c, o);
            if (lane == 0 && c) atomicAdd(&sCnt, c);
            __syncthreads();
            if (tid == 0) g_M[b] = sCnt;
        }

        int i = s * 113 + tid;           // one thread per box
        if (tid < 113 && i < NB) {
            float ki = skey[i];
            if (ki > 0.0f) {
                const float4* k4 = (const float4*)skey;
                int rank = 0;
                #pragma unroll 4
                for (int w = 0; w < NKPAD / 4; w++) {
                    float4 v = k4[w];
                    int j = w << 2;
                    rank += (v.x > ki) | ((v.x == ki) & (j     < i));
                    rank += (v.y > ki) | ((v.y == ki) & (j + 1 < i));
                    rank += (v.z > ki) | ((v.z == ki) & (j + 2 < i));
                    rank += (v.w > ki) | ((v.w == ki) & (j + 3 < i));
                }
                int a = i / 361, rem = i - a * 361;
                int hh = rem / 19, ww = rem - hh * 19;
                const float* p = ob + (a * 25) * 361 + rem;
                float cx = (1.0f / (1.0f + expf(-p[0]))   + (float)ww) / 19.0f;
                float cy = (1.0f / (1.0f + expf(-p[361])) + (float)hh) / 19.0f;
                float bw = expf(p[722])  * (ANCW[a] / 19.0f);
                float bh = expf(p[1083]) * (ANCH[a] / 19.0f);
                float4 v0 = make_float4(cx - bw * 0.5f, cx + bw * 0.5f,
                                        cy - bh * 0.5f, cy + bh * 0.5f);
                float4 v1 = make_float4(bw, bh, 0.0f, 0.0f);
                *(float4*)&g_boxes[b][rank][0] = v0;
                *(float4*)&g_boxes[b][rank][4] = v1;
            }
        }
    }

    grid_sync(sGen + 1);

    // ================= Phase B: suppression + GT bitmasks ================
    {
        const int b = blk >> 4, s = blk & 15;
        const int M = g_M[b];
        const int nw32 = (M + 31) >> 5;
        const int wb = (s << 3) + warp;          // warp within batch, 0..127

        if (wb < 96) {                            // box-vs-box masks
            unsigned* mask32 = (unsigned*)g_mask;
            const int G = (M + 3) >> 2;
            for (int g = wb; g < G; g += 96) {
                int r0 = g << 2;
                float4 R0[4], R1[4];
                #pragma unroll
                for (int d = 0; d < 4; d++) {
                    int ii = min(r0 + d, M - 1);
                    R0[d] = *(const float4*)&g_boxes[b][ii][0];
                    R1[d] = *(const float4*)&g_boxes[b][ii][4];
                }
                #pragma unroll 2
                for (int w = r0 >> 5; w < nw32; w++) {
                    int j = (w << 5) + lane, jc = min(j, M - 1);
                    float4 C0 = *(const float4*)&g_boxes[b][jc][0];
                    float4 C1 = *(const float4*)&g_boxes[b][jc][4];
                    #pragma unroll
                    for (int d = 0; d < 4; d++) {
                        int ii = r0 + d;
                        bool sp = (j > ii) && (j < M) && (ii < M) &&
                                  iou_gt(R0[d], R1[d], C0, C1, 0.45f);
                        unsigned bal = __ballot_sync(0xffffffffu, sp);
                        if (lane == d && ii < M)
                            mask32[((size_t)(b * NB + ii)) * NW32 + w] = bal;
                    }
                }
            }
        } else {                                  // GT bitmasks (blocks s>=12)
            unsigned* gtm32 = (unsigned*)g_gtm;
            const int ntasks = 50 * nw32;
            for (int task = wb - 96; task < ntasks; task += 32) {
                int t = task / nw32, w = task - t * nw32;
                float gx = sg[t * 5 + 1], gy = sg[t * 5 + 2];
                float gw = sg[t * 5 + 3], gh = sg[t * 5 + 4];
                float4 G0 = make_float4(gx - gw * 0.5f, gx + gw * 0.5f,
                                        gy - gh * 0.5f, gy + gh * 0.5f);
                float4 G1 = make_float4(gw, gh, 0.0f, 0.0f);
                int j = (w << 5) + lane, jc = min(j, M - 1);
                float4 C0 = *(const float4*)&g_boxes[b][jc][0];
                float4 C1 = *(const float4*)&g_boxes[b][jc][4];
                bool sp = (j < M) && iou_gt(G0, G1, C0, C1, 0.5f);
                unsigned bal = __ballot_sync(0xffffffffu, sp);
                if (lane == 0)
                    gtm32[((size_t)(b * 50 + t)) * NW32 + w] = bal;
            }
        }
    }

    grid_sync(sGen + 2);

    // ================= Phase C: serial chain + stats (blocks 0..7) =======
    if (blk >= 8) return;
    {
        const int b = blk;
        const int M = g_M[b];

        if (tid == 0) sCorr = 0;
        for (int t = tid; t < 250; t += NTHR) sg[t] = tgt[b * 250 + t];
        __syncthreads();

        if (tid == 32) {                 // GT validity prefix (serial 50)
            unsigned long long gv = 0ULL;
            int v = 1, tb = 0;
            for (int t = 0; t < 50; t++) {
                if (sg[t * 5 + 1] == 0.0f) v = 0;
                gv |= (unsigned long long)v << t; tb += v;
            }
            sGV = gv; sTot = tb;
        }

        if (warp == 0) {                 // greedy NMS, 8-box chunks, mod-3 bufs
            const unsigned long long* mb = g_mask + (size_t)b * NB * NW64;
            const bool ld = (lane < NW64);
            unsigned long long removed = 0ULL;
            unsigned long long buf[3][8];
            #pragma unroll
            for (int ph = 0; ph < 3; ph++)
                #pragma unroll
                for (int d = 0; d < 8; d++) {
                    int r = ph * 8 + d;
                    buf[ph][d] = (ld && r < M) ? mb[(size_t)r * NW64 + lane] : 0ULL;
                }
            for (int base = 0; base < M; base += 24) {
                #pragma unroll
                for (int ph = 0; ph < 3; ph++) {
                    int bb = base + ph * 8;
                    if (bb < M) {
                        int w0 = bb >> 6, sh = bb & 63;
                        unsigned long long sub = 0ULL;   // 8x8 intra submatrix
                        #pragma unroll
                        for (int d = 0; d < 8; d++)
                            sub |= ((buf[ph][d] >> sh) & 0xFFULL) << (8 * d);
                        unsigned long long sub_b = __shfl_sync(0xffffffffu, sub, w0);
                        unsigned long long rw    = __shfl_sync(0xffffffffu, removed, w0);
                        unsigned supp = (unsigned)((rw >> sh) & 0xFFULL);
                        unsigned dec = 0;
                        int lim = min(8, M - bb);
                        #pragma unroll
                        for (int d = 0; d < 8; d++)
                            if (d < lim && !((supp >> d) & 1u)) {
                                dec  |= 1u << d;
                                supp |= (unsigned)((sub_b >> (8 * d)) & 0xFFULL);
                            }
                        #pragma unroll
                        for (int d = 0; d < 8; d++)
                            if (dec & (1u << d)) removed |= buf[ph][d];
                        int nb2 = bb + 24;
                        #pragma unroll
                        for (int d = 0; d < 8; d++)
                            buf[ph][d] = (ld && nb2 + d < M)
                                       ? mb[(size_t)(nb2 + d) * NW64 + lane] : 0ULL;
                    }
                }
            }
            skeep[lane] = ld ? removed : 0ULL;
            int pc = ld ? __popcll(removed) : 0;
            #pragma unroll
            for (int o = 16; o; o >>= 1) pc += __shfl_xor_sync(0xffffffffu, pc, o);
            if (lane == 0) sProp = M - pc;
        }
        __syncthreads();

        // correct: one lane per GT, AND precomputed masks vs kept set
        if (tid < 50 && ((sGV >> tid) & 1ULL)) {
            const unsigned long long* gm = g_gtm[b][tid];
            bool any = false;
            #pragma unroll
            for (int w = 0; w < NW64; w++)
                any |= (gm[w] & ~skeep[w]) != 0ULL;
            if (any) atomicAdd(&sCorr, 1);
        }
        __syncthreads();

        if (tid == 0) {
            g_part[b][0] = sTot; g_part[b][1] = sProp; g_part[b][2] = sCorr;
            __threadfence();
            int tk = atomicAdd(&g_ticket, 1);
            if (tk == 7) {               // last batch-block finalizes
                __threadfence();
                int T = 0, P = 0, C = 0;
                for (int i = 0; i < 8; i++) {
                    T += g_part[i][0]; P += g_part[i][1]; C += g_part[i][2];
                }
                float tf = (float)T, pf = (float)P, cf = (float)C;
                float prec = cf / (pf + 1e-6f);
                float rec  = cf / (tf + 1e-6f);
                float f    = 2.0f * prec * rec / (prec + rec + 1e-6f);
                outp[0] = tf; outp[1] = pf; outp[2] = cf;
                outp[3] = prec; outp[4] = rec; outp[5] = f;
                atomicExch(&g_ticket, 0);   // reset for next replay
            }
        }
    }
}

extern "C" void kernel_launch(void* const* d_in, const int* in_sizes, int n_in,
                              void* d_out, int out_size) {
    const float* output = (const float*)d_in[0];  // [8,125,19,19]
    const float* target = (const float*)d_in[1];  // [8,250]
    fused_kernel<<<NBLK, NTHR>>>(output, target, (float*)d_out);
}

// round 7
// speedup vs baseline: 3.4097x; 1.0666x over previous
#include <cuda_runtime.h>
#include <math.h>

#define NB     1805          // 5*19*19 boxes per batch
#define NBP    1824          // padded list capacity
#define NW64   29            // ceil(1805/64) u64 words per mask row
#define NW32   58            // u32 view
#define NBLK   128
#define NTHR   256

// SoA decoded boxes (indexed by rank)
__device__ float g_bx1[8][NBP], g_bx2[8][NBP];
__device__ float g_by1[8][NBP], g_by2[8][NBP];
__device__ float g_bw [8][NBP], g_bh [8][NBP];
__device__ int   g_M[8];
__device__ unsigned long long g_mask[8ULL * NB * NW64];  // ~3.35MB, zero-init
__device__ unsigned long long g_gtm[8][50][NW64];        // GT IoU>0.5 bitmasks
__device__ int   g_part[8][3];
__device__ int   g_ticket = 0;
__device__ unsigned          g_count = 0;
__device__ volatile unsigned g_gen   = 0;

__constant__ float ANCW[5] = {1.3221f, 3.19275f, 5.05587f, 9.47112f, 11.2364f};
__constant__ float ANCH[5] = {1.73145f, 4.00944f, 8.09892f, 4.84053f, 10.0071f};

// IoU > thr with explicit RN ops + IEEE div (matches jax f32; uarea=0 -> NaN -> false)
__device__ __forceinline__ bool iou_gt(
    float ax1, float ax2, float ay1, float ay2, float aw, float ah,
    float bx1, float bx2, float by1, float by2, float bw, float bh, float thr) {
    float uw = __fsub_rn(fmaxf(ax2, bx2), fminf(ax1, bx1));
    float uh = __fsub_rn(fmaxf(ay2, by2), fminf(ay1, by1));
    float cw = __fsub_rn(__fadd_rn(aw, bw), uw);
    float ch = __fsub_rn(__fadd_rn(ah, bh), uh);
    float carea = (cw > 0.0f && ch > 0.0f) ? __fmul_rn(cw, ch) : 0.0f;
    float uarea = __fsub_rn(__fadd_rn(__fmul_rn(aw, ah), __fmul_rn(bw, bh)), carea);
    return __fdiv_rn(carea, uarea) > thr;
}

__device__ __forceinline__ void grid_sync_helper(unsigned target) {
    __threadfence();
    __syncthreads();
    if (threadIdx.x == 0) {
        unsigned t = atomicAdd(&g_count, 1u);
        if (t == NBLK - 1) {
            g_count = 0;
            __threadfence();
            g_gen = target;
        } else {
            while (g_gen != target) __nanosleep(64);
        }
    }
    __syncthreads();
    __threadfence();
}

extern "C" __global__ void __launch_bounds__(NTHR)
fused_kernel(const float* __restrict__ out,    // [8,125,19,19]
             const float* __restrict__ tgt,    // [8,250]
             float* __restrict__ outp)         // [6]
{
    __shared__ unsigned long long slist[NBP];  // valid-key u64 sort keys
    __shared__ float sg[252];
    __shared__ unsigned long long skeep[32];
    __shared__ unsigned long long sGV;
    __shared__ unsigned sGen;
    __shared__ int sCnt, sTot, sProp, sCorr;

    const int blk = blockIdx.x;          // 0..127
    const int tid = threadIdx.x;
    const int lane = tid & 31, warp = tid >> 5;
    const int b = blk >> 4, s = blk & 15;

    // ================= Phase A: compact valid keys + rank + decode =======
    {
        const float* ob = out + (size_t)b * 125 * 361;

        if (tid == 0) { sGen = g_gen; sCnt = 0; }
        if (s >= 12)   // GT staging for phase-B GT warps
            for (int t = tid; t < 250; t += NTHR) sg[t] = tgt[b * 250 + t];
        __syncthreads();

        // ballot-compacted valid list as u64 keys (desc key, asc idx order)
        for (int r0 = 0; r0 < NB; r0 += NTHR) {
            int r = r0 + tid;
            bool v = false;
            unsigned long long k64 = 0ULL;
            if (r < NB) {
                int a = r / 361, rem = r - a * 361;
                float k = ob[(a * 25 + 4) * 361 + rem];   // raw conf logit
                if (k > 0.0f) {                            // sigmoid > 0.5
                    v = true;
                    k64 = ((unsigned long long)__float_as_uint(k) << 32)
                        | (unsigned)(NB - r);
                }
            }
            unsigned bal = __ballot_sync(0xffffffffu, v);
            int base = 0;
            if (lane == 0 && bal) base = atomicAdd(&sCnt, __popc(bal));
            base = __shfl_sync(0xffffffffu, base, 0);
            if (v) slist[base + __popc(bal & ((1u << lane) - 1u))] = k64;
        }
        __syncthreads();
        const int M = sCnt;
        if (s == 0 && tid == 0) g_M[b] = M;
        const int Mp = (M + 3) & ~3;
        if (tid < Mp - M) slist[M + tid] = 0ULL;          // pad (never outranks)
        __syncthreads();

        // rank + decode: one thread per original box in this 113-slice
        int i = s * 113 + tid;
        if (tid < 113 && i < NB) {
            int a = i / 361, rem = i - a * 361;
            float ki = ob[(a * 25 + 4) * 361 + rem];
            if (ki > 0.0f) {
                unsigned long long k64 =
                    ((unsigned long long)__float_as_uint(ki) << 32)
                    | (unsigned)(NB - i);
                const ulonglong2* l2 = (const ulonglong2*)slist;
                int rank = 0;
                #pragma unroll 4
                for (int w = 0; w < Mp >> 1; w += 2) {
                    ulonglong2 p = l2[w], q = l2[w + 1];
                    rank += (p.x > k64) + (p.y > k64) + (q.x > k64) + (q.y > k64);
                }
                int hh = rem / 19, ww = rem - hh * 19;
                const float* p = ob + (a * 25) * 361 + rem;
                float cx = (1.0f / (1.0f + expf(-p[0]))   + (float)ww) / 19.0f;
                float cy = (1.0f / (1.0f + expf(-p[361])) + (float)hh) / 19.0f;
                float bw = expf(p[722])  * (ANCW[a] / 19.0f);
                float bh = expf(p[1083]) * (ANCH[a] / 19.0f);
                g_bx1[b][rank] = cx - bw * 0.5f;
                g_bx2[b][rank] = cx + bw * 0.5f;
                g_by1[b][rank] = cy - bh * 0.5f;
                g_by2[b][rank] = cy + bh * 0.5f;
                g_bw [b][rank] = bw;
                g_bh [b][rank] = bh;
            }
        }
    }

    grid_sync_helper(sGen + 1);

    // ================= Phase B: suppression + GT bitmasks (SoA reads) ====
    {
        const int M = g_M[b];
        const int nw32 = (M + 31) >> 5;
        const int wb = (s << 3) + warp;          // warp within batch, 0..127

        if (wb < 96) {                            // box-vs-box masks
            unsigned* mask32 = (unsigned*)g_mask;
            const int G = (M + 3) >> 2;
            for (int g = wb; g < G; g += 96) {
                int r0 = g << 2;
                float rx1[4], rx2[4], ry1[4], ry2[4], rw[4], rh[4];
                #pragma unroll
                for (int d = 0; d < 4; d++) {
                    int ii = min(r0 + d, M - 1);
                    rx1[d] = g_bx1[b][ii]; rx2[d] = g_bx2[b][ii];
                    ry1[d] = g_by1[b][ii]; ry2[d] = g_by2[b][ii];
                    rw[d]  = g_bw [b][ii]; rh[d]  = g_bh [b][ii];
                }
                #pragma unroll 2
                for (int w = r0 >> 5; w < nw32; w++) {
                    int j = (w << 5) + lane, jc = min(j, M - 1);
                    float cx1 = g_bx1[b][jc], cx2 = g_bx2[b][jc];
                    float cy1 = g_by1[b][jc], cy2 = g_by2[b][jc];
                    float cw_ = g_bw [b][jc], ch_ = g_bh [b][jc];
                    #pragma unroll
                    for (int d = 0; d < 4; d++) {
                        int ii = r0 + d;
                        bool sp = (j > ii) && (j < M) && (ii < M) &&
                                  iou_gt(rx1[d], rx2[d], ry1[d], ry2[d], rw[d], rh[d],
                                         cx1, cx2, cy1, cy2, cw_, ch_, 0.45f);
                        unsigned bal = __ballot_sync(0xffffffffu, sp);
                        if (lane == d && ii < M)
                            mask32[((size_t)(b * NB + ii)) * NW32 + w] = bal;
                    }
                }
            }
        } else {                                  // GT bitmasks (blocks s>=12)
            unsigned* gtm32 = (unsigned*)g_gtm;
            const int ntasks = 50 * nw32;
            for (int task = wb - 96; task < ntasks; task += 32) {
                int t = task / nw32, w = task - t * nw32;
                float gx = sg[t * 5 + 1], gy = sg[t * 5 + 2];
                float gw = sg[t * 5 + 3], gh = sg[t * 5 + 4];
                float gx1 = gx - gw * 0.5f, gx2 = gx + gw * 0.5f;
                float gy1 = gy - gh * 0.5f, gy2 = gy + gh * 0.5f;
                int j = (w << 5) + lane, jc = min(j, M - 1);
                float cx1 = g_bx1[b][jc], cx2 = g_bx2[b][jc];
                float cy1 = g_by1[b][jc], cy2 = g_by2[b][jc];
                float cw_ = g_bw [b][jc], ch_ = g_bh [b][jc];
                bool sp = (j < M) &&
                          iou_gt(gx1, gx2, gy1, gy2, gw, gh,
                                 cx1, cx2, cy1, cy2, cw_, ch_, 0.5f);
                unsigned bal = __ballot_sync(0xffffffffu, sp);
                if (lane == 0)
                    gtm32[((size_t)(b * 50 + t)) * NW32 + w] = bal;
            }
        }
    }

    grid_sync_helper(sGen + 2);

    // ================= Phase C: serial chain + stats (blocks 0..7) =======
    if (blk >= 8) return;
    {
        const int bb_ = blk;
        const int M = g_M[bb_];

        if (tid == 0) sCorr = 0;
        for (int t = tid; t < 250; t += NTHR) sg[t] = tgt[bb_ * 250 + t];
        __syncthreads();

        if (tid == 32) {                 // GT validity prefix (serial 50)
            unsigned long long gv = 0ULL;
            int v = 1, tb = 0;
            for (int t = 0; t < 50; t++) {
                if (sg[t * 5 + 1] == 0.0f) v = 0;
                gv |= (unsigned long long)v << t; tb += v;
            }
            sGV = gv; sTot = tb;
        }

        if (warp == 0) {                 // greedy NMS, 8-box chunks, mod-3 bufs
            const unsigned long long* mb = g_mask + (size_t)bb_ * NB * NW64;
            const bool ld = (lane < NW64);
            unsigned long long removed = 0ULL;
            unsigned long long buf[3][8];
            #pragma unroll
            for (int ph = 0; ph < 3; ph++)
                #pragma unroll
                for (int d = 0; d < 8; d++) {
                    int r = ph * 8 + d;
                    buf[ph][d] = (ld && r < M) ? mb[(size_t)r * NW64 + lane] : 0ULL;
                }
            for (int base = 0; base < M; base += 24) {
                #pragma unroll
                for (int ph = 0; ph < 3; ph++) {
                    int bb = base + ph * 8;
                    if (bb < M) {
                        int w0 = bb >> 6, sh = bb & 63;
                        unsigned long long sub = 0ULL;   // 8x8 intra submatrix
                        #pragma unroll
                        for (int d = 0; d < 8; d++)
                            sub |= ((buf[ph][d] >> sh) & 0xFFULL) << (8 * d);
                        unsigned long long sub_b = __shfl_sync(0xffffffffu, sub, w0);
                        unsigned long long rw    = __shfl_sync(0xffffffffu, removed, w0);
                        unsigned supp = (unsigned)((rw >> sh) & 0xFFULL);
                        unsigned dec = 0;
                        int lim = min(8, M - bb);
                        #pragma unroll
                        for (int d = 0; d < 8; d++)
                            if (d < lim && !((supp >> d) & 1u)) {
                                dec  |= 1u << d;
                                supp |= (unsigned)((sub_b >> (8 * d)) & 0xFFULL);
                            }
                        #pragma unroll
                        for (int d = 0; d < 8; d++)
                            if (dec & (1u << d)) removed |= buf[ph][d];
                        int nb2 = bb + 24;
                        #pragma unroll
                        for (int d = 0; d < 8; d++)
                            buf[ph][d] = (ld && nb2 + d < M)
                                       ? mb[(size_t)(nb2 + d) * NW64 + lane] : 0ULL;
                    }
                }
            }
            skeep[lane] = ld ? removed : 0ULL;
            int pc = ld ? __popcll(removed) : 0;
            #pragma unroll
            for (int o = 16; o; o >>= 1) pc += __shfl_xor_sync(0xffffffffu, pc, o);
            if (lane == 0) sProp = M - pc;
        }
        __syncthreads();

        // correct: one lane per GT, AND precomputed masks vs kept set
        if (tid < 50 && ((sGV >> tid) & 1ULL)) {
            const unsigned long long* gm = g_gtm[bb_][tid];
            bool any = false;
            #pragma unroll
            for (int w = 0; w < NW64; w++)
                any |= (gm[w] & ~skeep[w]) != 0ULL;
            if (any) atomicAdd(&sCorr, 1);
        }
        __syncthreads();

        if (tid == 0) {
            g_part[bb_][0] = sTot; g_part[bb_][1] = sProp; g_part[bb_][2] = sCorr;
            __threadfence();
            int tk = atomicAdd(&g_ticket, 1);
            if (tk == 7) {               // last batch-block finalizes
                __threadfence();
                int T = 0, P = 0, C = 0;
                for (int i = 0; i < 8; i++) {
                    T += g_part[i][0]; P += g_part[i][1]; C += g_part[i][2];
                }
                float tf = (float)T, pf = (float)P, cf = (float)C;
                float prec = cf / (pf + 1e-6f);
                float rec  = cf / (tf + 1e-6f);
                float f    = 2.0f * prec * rec / (prec + rec + 1e-6f);
                outp[0] = tf; outp[1] = pf; outp[2] = cf;
                outp[3] = prec; outp[4] = rec; outp[5] = f;
                atomicExch(&g_ticket, 0);   // reset for next replay
            }
        }
    }
}

extern "C" void kernel_launch(void* const* d_in, const int* in_sizes, int n_in,
                              void* d_out, int out_size) {
    const float* output = (const float*)d_in[0];  // [8,125,19,19]
    const float* target = (const float*)d_in[1];  // [8,250]
    fused_kernel<<<NBLK, NTHR>>>(output, target, (float*)d_out);
}